// round 13
// baseline (speedup 1.0000x reference)
#include <cuda_runtime.h>
#include <math.h>

#define BATCH   256
#define NPTS    20000
#define TSTEPS  10
#define LAT     10
#define BPB     5              // integrate blocks per batch
#define PPB     (NPTS / BPB)   // 4000 points per block
#define ITHREADS 512
#define COEF_PER_BATCH (TSTEPS * 256 * 8)   // 20480 floats = 80 KB
#define NSBLK   40             // sort blocks: 40*512 >= NPTS

// ---- device scratch (no allocations allowed) ----
__device__ float  g_coef[BATCH * COEF_PER_BATCH];   // [b][t][cell(16x16)][8]
__device__ float  g_a4[BATCH * 256];                // encoder layer-4 activations
__device__ int    g_order[NPTS];
__device__ float2 g_tps[NPTS];
__device__ int    g_bhist[NSBLK][256];
__device__ int    g_bbase[NSBLK][256];

__device__ __forceinline__ float tanh_fast(float x) {
    float y;
    asm("tanh.approx.f32 %0, %1;" : "=f"(y) : "f"(x));
    return y;
}

__device__ __forceinline__ int cell_of(float2 P) {
    int ui = min(max(__float2int_rd((P.x + 2.5f) * 3.0f), 0), 15);
    int vi = min(max(__float2int_rd((P.y + 2.5f) * 3.0f), 0), 15);
    return ui * 16 + vi;
}

// ============================================================================
// Counting sort by initial grid cell — 3 kernels, NO global atomics.
// ============================================================================
__global__ void sort_count_kernel(const float* __restrict__ tpl)
{
    __shared__ int lh[256];
    const int tid = threadIdx.x;
    if (tid < 256) lh[tid] = 0;
    __syncthreads();
    int p = blockIdx.x * 512 + tid;
    if (p < NPTS) atomicAdd(&lh[cell_of(((const float2*)tpl)[p])], 1);
    __syncthreads();
    if (tid < 256) g_bhist[blockIdx.x][tid] = lh[tid];
}

__global__ void sort_scan_kernel()
{
    __shared__ int tmp[256];
    const int c = threadIdx.x;
    int total = 0;
    #pragma unroll
    for (int bk = 0; bk < NSBLK; bk++) total += g_bhist[bk][c];
    tmp[c] = total;
    __syncthreads();
    #pragma unroll
    for (int off = 1; off < 256; off <<= 1) {
        int x = (c >= off) ? tmp[c - off] : 0;
        __syncthreads();
        tmp[c] += x;
        __syncthreads();
    }
    int running = tmp[c] - total;
    #pragma unroll
    for (int bk = 0; bk < NSBLK; bk++) {
        g_bbase[bk][c] = running;
        running += g_bhist[bk][c];
    }
}

__global__ void sort_scatter_kernel(const float* __restrict__ tpl)
{
    __shared__ int lh[256];
    __shared__ int lbase[256];
    const int tid = threadIdx.x;
    if (tid < 256) {
        lh[tid] = 0;
        lbase[tid] = g_bbase[blockIdx.x][tid];
    }
    __syncthreads();
    int p = blockIdx.x * 512 + tid;
    if (p < NPTS) {
        float2 P = ((const float2*)tpl)[p];
        int c = cell_of(P);
        int idx = lbase[c] + atomicAdd(&lh[c], 1);
        g_order[idx] = p;
        g_tps[idx] = P;
    }
}

// ============================================================================
// Encoder layers 1-4, split into 2 halo-free row-halves per batch.
// Grid 2*BATCH, 512 threads. k=2,s=2 convs never cross the half boundary.
// ============================================================================
__global__ __launch_bounds__(512)
void enc_kernel(const float* __restrict__ obs,
    const float* __restrict__ w1, const float* __restrict__ b1,
    const float* __restrict__ w2, const float* __restrict__ b2,
    const float* __restrict__ w3, const float* __restrict__ b3,
    const float* __restrict__ w4, const float* __restrict__ b4)
{
    __shared__ float OB[4096];
    __shared__ float A1[2048];
    __shared__ float A2[1024];
    __shared__ float A3[512];
    const int b = blockIdx.x >> 1;
    const int h = blockIdx.x & 1;
    const int tid = threadIdx.x;

    // stage obs rows [h*32, h*32+32) of both channels (1024 float4)
    {
        const float4* src = (const float4*)obs;
        float4* dst = (float4*)OB;
        #pragma unroll
        for (int it = 0; it < 2; it++) {
            int i = tid + it * 512;                 // i < 1024
            int ci = i >> 9, row = (i >> 4) & 31, c4 = i & 15;
            dst[i] = src[b*2048 + ci*1024 + (h*32 + row)*16 + c4];
        }
    }
    __syncthreads();

    // layer1 half: [2,32,64] -> [4,16,32]  (2048 outputs)
    #pragma unroll
    for (int it = 0; it < 4; it++) {
        int n = tid + it * 512;
        int o = n >> 9, r = (n >> 5) & 15, c = n & 31;
        float s = b1[o];
        #pragma unroll
        for (int ci = 0; ci < 2; ci++)
            #pragma unroll
            for (int m = 0; m < 2; m++) {
                float2 xv = ((const float2*)&OB[ci*2048 + (2*r+m)*64])[c];
                s += xv.x * w1[o*8 + ci*4 + m*2] + xv.y * w1[o*8 + ci*4 + m*2 + 1];
            }
        A1[n] = tanh_fast(s);
    }
    __syncthreads();
    // layer2 half: -> [8,8,16]  (1024)
    #pragma unroll
    for (int it = 0; it < 2; it++) {
        int n = tid + it * 512;
        int o = n >> 7, r = (n >> 4) & 7, c = n & 15;
        float s = b2[o];
        #pragma unroll
        for (int ci = 0; ci < 4; ci++)
            #pragma unroll
            for (int m = 0; m < 2; m++) {
                float2 xv = ((const float2*)&A1[ci*512 + (2*r+m)*32])[c];
                s += xv.x * w2[o*16 + ci*4 + m*2] + xv.y * w2[o*16 + ci*4 + m*2 + 1];
            }
        A2[n] = tanh_fast(s);
    }
    __syncthreads();
    // layer3 half: -> [16,4,8]  (512)
    {
        int n = tid;
        int o = n >> 5, r = (n >> 3) & 3, c = n & 7;
        float s = b3[o];
        #pragma unroll
        for (int ci = 0; ci < 8; ci++)
            #pragma unroll
            for (int m = 0; m < 2; m++) {
                float2 xv = ((const float2*)&A2[ci*128 + (2*r+m)*16])[c];
                s += xv.x * w3[o*32 + ci*4 + m*2] + xv.y * w3[o*32 + ci*4 + m*2 + 1];
            }
        A3[n] = tanh_fast(s);
    }
    __syncthreads();
    // layer4 half: -> [16,2,4]  (128) -> global g_a4[b][o][h*2+r][c]
    if (tid < 128) {
        int o = tid >> 3, r = (tid >> 2) & 1, c = tid & 3;
        float s = b4[o];
        #pragma unroll
        for (int ci = 0; ci < 16; ci++)
            #pragma unroll
            for (int m = 0; m < 2; m++) {
                float2 xv = ((const float2*)&A3[ci*32 + (2*r+m)*8])[c];
                s += xv.x * w4[o*64 + ci*4 + m*2] + xv.y * w4[o*64 + ci*4 + m*2 + 1];
            }
        g_a4[b*256 + o*16 + (h*2 + r)*4 + c] = tanh_fast(s);
    }
}

// ============================================================================
// Linear + decoder + coefficient build, one block per (b, t). Grid 2560, 256 thr.
// ============================================================================
__global__ __launch_bounds__(256)
void dec_kernel(const float* __restrict__ lw, const float* __restrict__ lb,
    const float* __restrict__ dlw,
    const float* __restrict__ dw1, const float* __restrict__ dw2,
    const float* __restrict__ dw3)
{
    __shared__ float RED[80];
    __shared__ float Z[LAT];
    __shared__ float H[64];
    __shared__ float O1[128];
    __shared__ float O2[256];
    __shared__ float VF[512];
    const int bt = blockIdx.x;
    const int b = bt / TSTEPS, t = bt - b * TSTEPS;
    const float scale = 0.1f * (float)(t + 1);
    const int tid = threadIdx.x;
    const float* a4 = g_a4 + b * 256;

    if (tid < 80) {
        int l = tid >> 3, seg = tid & 7;
        float s = 0.f;
        #pragma unroll
        for (int k = 0; k < 32; k++)
            s += a4[seg*32 + k] * lw[l*256 + seg*32 + k];
        RED[tid] = s;
    }
    __syncthreads();
    if (tid < LAT) {
        float s = lb[tid];
        #pragma unroll
        for (int k = 0; k < 8; k++) s += RED[tid*8 + k];
        Z[tid] = s;
    }
    __syncthreads();
    if (tid < 64) {
        float s = 0.f;
        #pragma unroll
        for (int l = 0; l < LAT; l++) s += Z[l] * dlw[tid*LAT + l];
        H[tid] = tanh_fast(scale * s);
    }
    __syncthreads();
    // convT1: 16->8, [2,2]->[4,4]  (128)
    if (tid < 128) {
        int o = tid >> 4, p = (tid >> 2) & 3, q = tid & 3;
        float s = 0.f;
        #pragma unroll
        for (int c = 0; c < 16; c++)
            s += H[c*4 + (p>>1)*2 + (q>>1)]
               * dw1[c*32 + o*4 + (1-(p&1))*2 + (1-(q&1))];
        O1[o*16 + p*4 + q] = tanh_fast(s);
    }
    __syncthreads();
    // convT2: 8->4, [4,4]->[8,8]  (256)
    {
        int o = tid >> 6, p = (tid >> 3) & 7, q = tid & 7;
        float s = 0.f;
        #pragma unroll
        for (int c = 0; c < 8; c++)
            s += O1[c*16 + (p>>1)*4 + (q>>1)]
               * dw2[c*16 + o*4 + (1-(p&1))*2 + (1-(q&1))];
        O2[o*64 + p*8 + q] = tanh_fast(s);
    }
    __syncthreads();
    // convT3: 4->2, [8,8]->[16,16]  (512), no tanh
    #pragma unroll
    for (int it = 0; it < 2; it++) {
        int n = tid + it * 256;
        int o = n >> 8, p = (n >> 4) & 15, q = n & 15;
        float s = 0.f;
        #pragma unroll
        for (int c = 0; c < 4; c++)
            s += O2[c*64 + (p>>1)*8 + (q>>1)]
               * dw3[c*8 + o*4 + (1-(p&1))*2 + (1-(q&1))];
        VF[o*256 + p*16 + q] = s;
    }
    __syncthreads();
    // coefficient table for this (b,t), prescaled by 3*dt
    float* cc = g_coef + (size_t)b * COEF_PER_BATCH + t * 2048;
    const float Sc = 0.3f;
    {
        int cell = tid;
        int i = cell >> 4, j = cell & 15;
        int i2 = min(i + 1, 15), j2 = min(j + 1, 15);
        float v00x = VF[i*16 + j],    v00y = VF[256 + i*16 + j];
        float v10x = VF[i2*16 + j],   v10y = VF[256 + i2*16 + j];
        float v01x = VF[i*16 + j2],   v01y = VF[256 + i*16 + j2];
        float v11x = VF[i2*16 + j2],  v11y = VF[256 + i2*16 + j2];
        float4 ca = make_float4(Sc*v00x, Sc*v00y, Sc*(v10x - v00x), Sc*(v10y - v00y));
        float4 cb = make_float4(Sc*(v01x - v00x), Sc*(v01y - v00y),
                                Sc*(v11x - v01x - v10x + v00x),
                                Sc*(v11y - v01y - v10y + v00y));
        float4* d = (float4*)(cc + cell * 8);
        d[0] = ca; d[1] = cb;
    }
}

// ============================================================================
// Integration over cell-sorted points (R9-proven shape: 80 KB table,
// 2 blocks/SM, 2 points per thread for ILP, no forced register cap).
// ============================================================================
__device__ __forceinline__ void euler_step(const float* sc, int t,
                                           float& u, float& v)
{
    float uf = floorf(u), vf = floorf(v);
    float fu = u - uf,    fv = v - vf;
    float idxf = fminf(fmaxf(uf * 16.0f + vf, 0.0f), 255.0f);
    int idx = __float2int_rz(idxf);
    const float4* c = (const float4*)&sc[(t << 11) + (idx << 3)];
    float4 ca = c[0];   // c00x c00y c10x c10y
    float4 cb = c[1];   // c01x c01y c11x c11y
    float fufv = fu * fv;
    u += ca.x + fu*ca.z + fv*cb.x + fufv*cb.z;
    v += ca.y + fu*ca.w + fv*cb.y + fufv*cb.w;
}

__global__ __launch_bounds__(ITHREADS, 2)
void integrate_kernel(float* __restrict__ out)
{
    extern __shared__ float sc[];     // 20480 floats: [t][cell][8]
    const int b   = blockIdx.x / BPB;
    const int blk = blockIdx.x % BPB;

    const float4* src = (const float4*)(g_coef + (size_t)b * COEF_PER_BATCH);
    float4* dst = (float4*)sc;
    #pragma unroll
    for (int i = 0; i < COEF_PER_BATCH / 4 / ITHREADS; i++)
        dst[threadIdx.x + i * ITHREADS] = src[threadIdx.x + i * ITHREADS];
    __syncthreads();

    float2* op2 = (float2*)out + (size_t)b * NPTS;
    const int pend = blk * PPB + PPB;
    for (int p0 = blk * PPB + threadIdx.x; p0 < pend; p0 += 2 * ITHREADS) {
        const int p1 = p0 + ITHREADS;
        const bool has1 = p1 < pend;
        float2 A = g_tps[p0];
        float2 Bp = has1 ? g_tps[p1] : make_float2(0.f, 0.f);
        int oa = g_order[p0];
        int ob = has1 ? g_order[p1] : 0;
        float ua = (A.x + 2.5f) * 3.0f,  va = (A.y + 2.5f) * 3.0f;
        float ub = (Bp.x + 2.5f) * 3.0f, vb = (Bp.y + 2.5f) * 3.0f;
        #pragma unroll
        for (int t = 0; t < TSTEPS; t++) {
            euler_step(sc, t, ua, va);
            euler_step(sc, t, ub, vb);
        }
        op2[oa] = make_float2(ua * (1.0f/3.0f) - 2.5f, va * (1.0f/3.0f) - 2.5f);
        if (has1)
            op2[ob] = make_float2(ub * (1.0f/3.0f) - 2.5f, vb * (1.0f/3.0f) - 2.5f);
    }
}

// ============================================================================
extern "C" void kernel_launch(void* const* d_in, const int* in_sizes, int n_in,
                              void* d_out, int out_size)
{
    const float* obs   = (const float*)d_in[0];
    const float* tpl   = (const float*)d_in[1];
    const float* ew1   = (const float*)d_in[2];
    const float* eb1   = (const float*)d_in[3];
    const float* ew2   = (const float*)d_in[4];
    const float* eb2   = (const float*)d_in[5];
    const float* ew3   = (const float*)d_in[6];
    const float* eb3   = (const float*)d_in[7];
    const float* ew4   = (const float*)d_in[8];
    const float* eb4   = (const float*)d_in[9];
    const float* elw   = (const float*)d_in[10];
    const float* elb   = (const float*)d_in[11];
    const float* dlw   = (const float*)d_in[12];
    const float* dw1   = (const float*)d_in[13];
    const float* dw2   = (const float*)d_in[14];
    const float* dw3   = (const float*)d_in[15];
    float* out = (float*)d_out;

    cudaFuncSetAttribute(integrate_kernel,
                         cudaFuncAttributeMaxDynamicSharedMemorySize,
                         COEF_PER_BATCH * 4);

    sort_count_kernel<<<NSBLK, 512>>>(tpl);
    sort_scan_kernel<<<1, 256>>>();
    sort_scatter_kernel<<<NSBLK, 512>>>(tpl);
    enc_kernel<<<BATCH * 2, 512>>>(obs, ew1, eb1, ew2, eb2, ew3, eb3, ew4, eb4);
    dec_kernel<<<BATCH * TSTEPS, 256>>>(elw, elb, dlw, dw1, dw2, dw3);
    integrate_kernel<<<BATCH * BPB, ITHREADS, COEF_PER_BATCH * 4>>>(out);
}

// round 14
// speedup vs baseline: 1.2205x; 1.2205x over previous
#include <cuda_runtime.h>
#include <math.h>

#define BATCH   256
#define NPTS    20000
#define TSTEPS  10
#define LAT     10
#define BPB     8              // integrate blocks per batch (wave-quantization fix)
#define PPB     (NPTS / BPB)   // 2500 points per block
#define ITHREADS 512
#define ETHREADS 512
#define COEF_PER_BATCH (TSTEPS * 256 * 8)   // 20480 floats = 80 KB
#define NSBLK   40             // sort blocks: 40*512 >= NPTS

// ---- device scratch (no allocations allowed) ----
__device__ float  g_coef[BATCH * COEF_PER_BATCH];   // [b][t][cell(16x16)][8]
__device__ int    g_order[NPTS];
__device__ float2 g_tps[NPTS];
__device__ int    g_bhist[NSBLK][256];
__device__ int    g_bbase[NSBLK][256];

__device__ __forceinline__ float tanh_fast(float x) {
    float y;
    asm("tanh.approx.f32 %0, %1;" : "=f"(y) : "f"(x));
    return y;
}

__device__ __forceinline__ int cell_of(float2 P) {
    int ui = min(max(__float2int_rd((P.x + 2.5f) * 3.0f), 0), 15);
    int vi = min(max(__float2int_rd((P.y + 2.5f) * 3.0f), 0), 15);
    return ui * 16 + vi;
}

// ============================================================================
// Counting sort by initial grid cell — 3 kernels, NO global atomics.
// ============================================================================
__global__ void sort_count_kernel(const float* __restrict__ tpl)
{
    __shared__ int lh[256];
    const int tid = threadIdx.x;
    if (tid < 256) lh[tid] = 0;
    __syncthreads();
    int p = blockIdx.x * 512 + tid;
    if (p < NPTS) atomicAdd(&lh[cell_of(((const float2*)tpl)[p])], 1);
    __syncthreads();
    if (tid < 256) g_bhist[blockIdx.x][tid] = lh[tid];
}

__global__ void sort_scan_kernel()
{
    __shared__ int tmp[256];
    const int c = threadIdx.x;
    int total = 0;
    #pragma unroll
    for (int bk = 0; bk < NSBLK; bk++) total += g_bhist[bk][c];
    tmp[c] = total;
    __syncthreads();
    #pragma unroll
    for (int off = 1; off < 256; off <<= 1) {
        int x = (c >= off) ? tmp[c - off] : 0;
        __syncthreads();
        tmp[c] += x;
        __syncthreads();
    }
    int running = tmp[c] - total;
    #pragma unroll
    for (int bk = 0; bk < NSBLK; bk++) {
        g_bbase[bk][c] = running;
        running += g_bhist[bk][c];
    }
}

__global__ void sort_scatter_kernel(const float* __restrict__ tpl)
{
    __shared__ int lh[256];
    __shared__ int lbase[256];
    const int tid = threadIdx.x;
    if (tid < 256) {
        lh[tid] = 0;
        lbase[tid] = g_bbase[blockIdx.x][tid];
    }
    __syncthreads();
    int p = blockIdx.x * 512 + tid;
    if (p < NPTS) {
        float2 P = ((const float2*)tpl)[p];
        int c = cell_of(P);
        int idx = lbase[c] + atomicAdd(&lh[c], 1);
        g_order[idx] = p;
        g_tps[idx] = P;
    }
}

// ============================================================================
// Fused encoder + decoder + coefficient build (R11-proven). One block per
// batch, 512 thr, HW tanh.approx. smem union (12288 floats = 48 KB).
// ============================================================================
#define OBS_  0
#define A1_   8192
#define A2_   0
#define A3_   2048
#define A4_   3072
#define RED_  11800
#define Z_    11900
#define ZD_   11910
#define H_    0
#define O1_   640
#define O2_   1920
#define VF_   4480

__global__ __launch_bounds__(ETHREADS)
void encdec_kernel(const float* __restrict__ obs,
    const float* __restrict__ w1, const float* __restrict__ b1,
    const float* __restrict__ w2, const float* __restrict__ b2,
    const float* __restrict__ w3, const float* __restrict__ b3,
    const float* __restrict__ w4, const float* __restrict__ b4,
    const float* __restrict__ lw, const float* __restrict__ lb,
    const float* __restrict__ dlw,
    const float* __restrict__ dw1, const float* __restrict__ dw2,
    const float* __restrict__ dw3)
{
    __shared__ float S[12288];
    const int b = blockIdx.x;
    const int tid = threadIdx.x;

    {
        const float4* src = (const float4*)(obs + (size_t)b * 8192);
        float4* dst = (float4*)&S[OBS_];
        #pragma unroll
        for (int i = 0; i < 4; i++) dst[tid + i * ETHREADS] = src[tid + i * ETHREADS];
    }
    __syncthreads();

    // layer1: [2,64,64] -> [4,32,32]  (4096 outputs)
    #pragma unroll
    for (int it = 0; it < 8; it++) {
        int n = tid + it * ETHREADS;
        int o = n >> 10, r = (n >> 5) & 31, c = n & 31;
        float s = b1[o];
        #pragma unroll
        for (int ci = 0; ci < 2; ci++)
            #pragma unroll
            for (int m = 0; m < 2; m++) {
                float2 xv = ((const float2*)&S[OBS_ + ci*4096 + (2*r+m)*64])[c];
                s += xv.x * w1[o*8 + ci*4 + m*2] + xv.y * w1[o*8 + ci*4 + m*2 + 1];
            }
        S[A1_ + n] = tanh_fast(s);
    }
    __syncthreads();
    // layer2: -> [8,16,16]  (2048)
    #pragma unroll
    for (int it = 0; it < 4; it++) {
        int n = tid + it * ETHREADS;
        int o = n >> 8, r = (n >> 4) & 15, c = n & 15;
        float s = b2[o];
        #pragma unroll
        for (int ci = 0; ci < 4; ci++)
            #pragma unroll
            for (int m = 0; m < 2; m++) {
                float2 xv = ((const float2*)&S[A1_ + ci*1024 + (2*r+m)*32])[c];
                s += xv.x * w2[o*16 + ci*4 + m*2] + xv.y * w2[o*16 + ci*4 + m*2 + 1];
            }
        S[A2_ + n] = tanh_fast(s);
    }
    __syncthreads();
    // layer3: -> [16,8,8]  (1024)
    #pragma unroll
    for (int it = 0; it < 2; it++) {
        int n = tid + it * ETHREADS;
        int o = n >> 6, r = (n >> 3) & 7, c = n & 7;
        float s = b3[o];
        #pragma unroll
        for (int ci = 0; ci < 8; ci++)
            #pragma unroll
            for (int m = 0; m < 2; m++) {
                float2 xv = ((const float2*)&S[A2_ + ci*256 + (2*r+m)*16])[c];
                s += xv.x * w3[o*32 + ci*4 + m*2] + xv.y * w3[o*32 + ci*4 + m*2 + 1];
            }
        S[A3_ + n] = tanh_fast(s);
    }
    __syncthreads();
    // layer4: -> [16,4,4]  (256)
    if (tid < 256) {
        int n = tid;
        int o = n >> 4, r = (n >> 2) & 3, c = n & 3;
        float s = b4[o];
        #pragma unroll
        for (int ci = 0; ci < 16; ci++)
            #pragma unroll
            for (int m = 0; m < 2; m++) {
                float2 xv = ((const float2*)&S[A3_ + ci*64 + (2*r+m)*8])[c];
                s += xv.x * w4[o*64 + ci*4 + m*2] + xv.y * w4[o*64 + ci*4 + m*2 + 1];
            }
        S[A4_ + n] = tanh_fast(s);
    }
    __syncthreads();
    if (tid < 80) {
        int l = tid >> 3, seg = tid & 7;
        float s = 0.f;
        #pragma unroll
        for (int k = 0; k < 32; k++)
            s += S[A4_ + seg*32 + k] * lw[l*256 + seg*32 + k];
        S[RED_ + tid] = s;
    }
    __syncthreads();
    if (tid < LAT) {
        float s = lb[tid];
        #pragma unroll
        for (int k = 0; k < 8; k++) s += S[RED_ + tid*8 + k];
        S[Z_ + tid] = s;
    }
    __syncthreads();

    // ---- decoder, all T-1 time scales in one pass ----
    if (tid < 64) {
        float s = 0.f;
        #pragma unroll
        for (int l = 0; l < LAT; l++) s += S[Z_ + l] * dlw[tid*LAT + l];
        S[ZD_ + tid] = s;
    }
    __syncthreads();
    for (int n = tid; n < 640; n += ETHREADS) {
        int t = n >> 6, k = n & 63;
        S[H_ + n] = tanh_fast(0.1f * (float)(t + 1) * S[ZD_ + k]);
    }
    __syncthreads();
    for (int n0 = tid; n0 < 1280; n0 += ETHREADS) {
        int t = n0 >> 7, r = n0 & 127;
        int o = r >> 4, p = (r >> 2) & 3, q = r & 3;
        float s = 0.f;
        #pragma unroll
        for (int c = 0; c < 16; c++)
            s += S[H_ + t*64 + c*4 + (p>>1)*2 + (q>>1)]
               * dw1[c*32 + o*4 + (1-(p&1))*2 + (1-(q&1))];
        S[O1_ + n0] = tanh_fast(s);
    }
    __syncthreads();
    for (int n0 = tid; n0 < 2560; n0 += ETHREADS) {
        int t = n0 >> 8, r = n0 & 255;
        int o = r >> 6, p = (r >> 3) & 7, q = r & 7;
        float s = 0.f;
        #pragma unroll
        for (int c = 0; c < 8; c++)
            s += S[O1_ + t*128 + c*16 + (p>>1)*4 + (q>>1)]
               * dw2[c*16 + o*4 + (1-(p&1))*2 + (1-(q&1))];
        S[O2_ + n0] = tanh_fast(s);
    }
    __syncthreads();
    for (int n0 = tid; n0 < 5120; n0 += ETHREADS) {
        int t = n0 >> 9, r = n0 & 511;
        int o = r >> 8, p = (r >> 4) & 15, q = r & 15;
        float s = 0.f;
        #pragma unroll
        for (int c = 0; c < 4; c++)
            s += S[O2_ + t*256 + c*64 + (p>>1)*8 + (q>>1)]
               * dw3[c*8 + o*4 + (1-(p&1))*2 + (1-(q&1))];
        S[VF_ + n0] = s;
    }
    __syncthreads();
    float* cc = g_coef + (size_t)b * COEF_PER_BATCH;
    const float Sc = 0.3f;
    for (int n0 = tid; n0 < 2560; n0 += ETHREADS) {
        int t = n0 >> 8, cell = n0 & 255;
        int i = cell >> 4, j = cell & 15;
        int i2 = min(i + 1, 15), j2 = min(j + 1, 15);
        const float* vf = &S[VF_ + t*512];
        float v00x = vf[i*16 + j],    v00y = vf[256 + i*16 + j];
        float v10x = vf[i2*16 + j],   v10y = vf[256 + i2*16 + j];
        float v01x = vf[i*16 + j2],   v01y = vf[256 + i*16 + j2];
        float v11x = vf[i2*16 + j2],  v11y = vf[256 + i2*16 + j2];
        float4 ca = make_float4(Sc*v00x, Sc*v00y, Sc*(v10x - v00x), Sc*(v10y - v00y));
        float4 cb = make_float4(Sc*(v01x - v00x), Sc*(v01y - v00y),
                                Sc*(v11x - v01x - v10x + v00x),
                                Sc*(v11y - v01y - v10y + v00y));
        float4* d = (float4*)(cc + (t*256 + cell) * 8);
        d[0] = ca; d[1] = cb;
    }
}

// ============================================================================
// Integration over cell-sorted points, 2 points per thread for ILP.
// BPB=8: grid 2048 -> 7 waves at 296 concurrent (1.2% tail waste).
// ============================================================================
__device__ __forceinline__ void euler_step(const float* sc, int t,
                                           float& u, float& v)
{
    float uf = floorf(u), vf = floorf(v);
    float fu = u - uf,    fv = v - vf;
    float idxf = fminf(fmaxf(uf * 16.0f + vf, 0.0f), 255.0f);
    int idx = __float2int_rz(idxf);
    const float4* c = (const float4*)&sc[(t << 11) + (idx << 3)];
    float4 ca = c[0];   // c00x c00y c10x c10y
    float4 cb = c[1];   // c01x c01y c11x c11y
    float fufv = fu * fv;
    u += ca.x + fu*ca.z + fv*cb.x + fufv*cb.z;
    v += ca.y + fu*ca.w + fv*cb.y + fufv*cb.w;
}

__global__ __launch_bounds__(ITHREADS, 2)
void integrate_kernel(float* __restrict__ out)
{
    extern __shared__ float sc[];     // 20480 floats: [t][cell][8]
    const int b   = blockIdx.x / BPB;
    const int blk = blockIdx.x % BPB;

    const float4* src = (const float4*)(g_coef + (size_t)b * COEF_PER_BATCH);
    float4* dst = (float4*)sc;
    #pragma unroll
    for (int i = 0; i < COEF_PER_BATCH / 4 / ITHREADS; i++)
        dst[threadIdx.x + i * ITHREADS] = src[threadIdx.x + i * ITHREADS];
    __syncthreads();

    float2* op2 = (float2*)out + (size_t)b * NPTS;
    const int pend = blk * PPB + PPB;
    for (int p0 = blk * PPB + threadIdx.x; p0 < pend; p0 += 2 * ITHREADS) {
        const int p1 = p0 + ITHREADS;
        const bool has1 = p1 < pend;
        float2 A = g_tps[p0];
        float2 Bp = has1 ? g_tps[p1] : make_float2(0.f, 0.f);
        int oa = g_order[p0];
        int ob = has1 ? g_order[p1] : 0;
        float ua = (A.x + 2.5f) * 3.0f,  va = (A.y + 2.5f) * 3.0f;
        float ub = (Bp.x + 2.5f) * 3.0f, vb = (Bp.y + 2.5f) * 3.0f;
        #pragma unroll
        for (int t = 0; t < TSTEPS; t++) {
            euler_step(sc, t, ua, va);
            euler_step(sc, t, ub, vb);
        }
        op2[oa] = make_float2(ua * (1.0f/3.0f) - 2.5f, va * (1.0f/3.0f) - 2.5f);
        if (has1)
            op2[ob] = make_float2(ub * (1.0f/3.0f) - 2.5f, vb * (1.0f/3.0f) - 2.5f);
    }
}

// ============================================================================
extern "C" void kernel_launch(void* const* d_in, const int* in_sizes, int n_in,
                              void* d_out, int out_size)
{
    const float* obs   = (const float*)d_in[0];
    const float* tpl   = (const float*)d_in[1];
    const float* ew1   = (const float*)d_in[2];
    const float* eb1   = (const float*)d_in[3];
    const float* ew2   = (const float*)d_in[4];
    const float* eb2   = (const float*)d_in[5];
    const float* ew3   = (const float*)d_in[6];
    const float* eb3   = (const float*)d_in[7];
    const float* ew4   = (const float*)d_in[8];
    const float* eb4   = (const float*)d_in[9];
    const float* elw   = (const float*)d_in[10];
    const float* elb   = (const float*)d_in[11];
    const float* dlw   = (const float*)d_in[12];
    const float* dw1   = (const float*)d_in[13];
    const float* dw2   = (const float*)d_in[14];
    const float* dw3   = (const float*)d_in[15];
    float* out = (float*)d_out;

    cudaFuncSetAttribute(integrate_kernel,
                         cudaFuncAttributeMaxDynamicSharedMemorySize,
                         COEF_PER_BATCH * 4);

    sort_count_kernel<<<NSBLK, 512>>>(tpl);
    sort_scan_kernel<<<1, 256>>>();
    sort_scatter_kernel<<<NSBLK, 512>>>(tpl);
    encdec_kernel<<<BATCH, ETHREADS>>>(obs, ew1, eb1, ew2, eb2, ew3, eb3, ew4, eb4,
                                       elw, elb, dlw, dw1, dw2, dw3);
    integrate_kernel<<<BATCH * BPB, ITHREADS, COEF_PER_BATCH * 4>>>(out);
}

// round 15
// speedup vs baseline: 1.3957x; 1.1435x over previous
#include <cuda_runtime.h>
#include <math.h>

#define BATCH   256
#define NPTS    20000
#define TSTEPS  10
#define LAT     10
#define BPB     5              // integrate blocks per batch (R11-proven)
#define PPB     (NPTS / BPB)   // 4000 points per block
#define ITHREADS 512
#define ETHREADS 512
#define COEF_PER_BATCH (TSTEPS * 256 * 8)   // 20480 floats = 80 KB
#define NSBLK   40             // sort blocks: 40*512 >= NPTS

// ---- device scratch (no allocations allowed) ----
__device__ float  g_coef[BATCH * COEF_PER_BATCH];   // [b][t][cell(16x16)][8] absolute-form
__device__ int    g_order[NPTS];
__device__ float2 g_tps[NPTS];
__device__ int    g_bhist[NSBLK][256];
__device__ int    g_bbase[NSBLK][256];

__device__ __forceinline__ float tanh_fast(float x) {
    float y;
    asm("tanh.approx.f32 %0, %1;" : "=f"(y) : "f"(x));
    return y;
}

__device__ __forceinline__ int cell_of(float2 P) {
    int ui = min(max(__float2int_rd((P.x + 2.5f) * 3.0f), 0), 15);
    int vi = min(max(__float2int_rd((P.y + 2.5f) * 3.0f), 0), 15);
    return ui * 16 + vi;
}

// ============================================================================
// Counting sort by initial grid cell — 3 kernels, NO global atomics.
// ============================================================================
__global__ void sort_count_kernel(const float* __restrict__ tpl)
{
    __shared__ int lh[256];
    const int tid = threadIdx.x;
    if (tid < 256) lh[tid] = 0;
    __syncthreads();
    int p = blockIdx.x * 512 + tid;
    if (p < NPTS) atomicAdd(&lh[cell_of(((const float2*)tpl)[p])], 1);
    __syncthreads();
    if (tid < 256) g_bhist[blockIdx.x][tid] = lh[tid];
}

__global__ void sort_scan_kernel()
{
    __shared__ int tmp[256];
    const int c = threadIdx.x;
    int total = 0;
    #pragma unroll
    for (int bk = 0; bk < NSBLK; bk++) total += g_bhist[bk][c];
    tmp[c] = total;
    __syncthreads();
    #pragma unroll
    for (int off = 1; off < 256; off <<= 1) {
        int x = (c >= off) ? tmp[c - off] : 0;
        __syncthreads();
        tmp[c] += x;
        __syncthreads();
    }
    int running = tmp[c] - total;
    #pragma unroll
    for (int bk = 0; bk < NSBLK; bk++) {
        g_bbase[bk][c] = running;
        running += g_bhist[bk][c];
    }
}

__global__ void sort_scatter_kernel(const float* __restrict__ tpl)
{
    __shared__ int lh[256];
    __shared__ int lbase[256];
    const int tid = threadIdx.x;
    if (tid < 256) {
        lh[tid] = 0;
        lbase[tid] = g_bbase[blockIdx.x][tid];
    }
    __syncthreads();
    int p = blockIdx.x * 512 + tid;
    if (p < NPTS) {
        float2 P = ((const float2*)tpl)[p];
        int c = cell_of(P);
        int idx = lbase[c] + atomicAdd(&lh[c], 1);
        g_order[idx] = p;
        g_tps[idx] = P;
    }
}

// ============================================================================
// Fused encoder + decoder + coefficient build (R11-proven structure).
// Epilogue now emits ABSOLUTE-form coefficients:
//   vel(u,v) = d00 + u*d10 + v*d01 + u*v*d11   (per cell, prescaled by 3*dt)
// where d00 = c00 - i*c10 - j*c01 + i*j*c11, d10 = c10 - j*c11,
//       d01 = c01 - i*c11, d11 = c11.
// ============================================================================
#define OBS_  0
#define A1_   8192
#define A2_   0
#define A3_   2048
#define A4_   3072
#define RED_  11800
#define Z_    11900
#define ZD_   11910
#define H_    0
#define O1_   640
#define O2_   1920
#define VF_   4480

__global__ __launch_bounds__(ETHREADS)
void encdec_kernel(const float* __restrict__ obs,
    const float* __restrict__ w1, const float* __restrict__ b1,
    const float* __restrict__ w2, const float* __restrict__ b2,
    const float* __restrict__ w3, const float* __restrict__ b3,
    const float* __restrict__ w4, const float* __restrict__ b4,
    const float* __restrict__ lw, const float* __restrict__ lb,
    const float* __restrict__ dlw,
    const float* __restrict__ dw1, const float* __restrict__ dw2,
    const float* __restrict__ dw3)
{
    __shared__ float S[12288];
    const int b = blockIdx.x;
    const int tid = threadIdx.x;

    {
        const float4* src = (const float4*)(obs + (size_t)b * 8192);
        float4* dst = (float4*)&S[OBS_];
        #pragma unroll
        for (int i = 0; i < 4; i++) dst[tid + i * ETHREADS] = src[tid + i * ETHREADS];
    }
    __syncthreads();

    // layer1: [2,64,64] -> [4,32,32]  (4096 outputs)
    #pragma unroll
    for (int it = 0; it < 8; it++) {
        int n = tid + it * ETHREADS;
        int o = n >> 10, r = (n >> 5) & 31, c = n & 31;
        float s = b1[o];
        #pragma unroll
        for (int ci = 0; ci < 2; ci++)
            #pragma unroll
            for (int m = 0; m < 2; m++) {
                float2 xv = ((const float2*)&S[OBS_ + ci*4096 + (2*r+m)*64])[c];
                s += xv.x * w1[o*8 + ci*4 + m*2] + xv.y * w1[o*8 + ci*4 + m*2 + 1];
            }
        S[A1_ + n] = tanh_fast(s);
    }
    __syncthreads();
    // layer2: -> [8,16,16]  (2048)
    #pragma unroll
    for (int it = 0; it < 4; it++) {
        int n = tid + it * ETHREADS;
        int o = n >> 8, r = (n >> 4) & 15, c = n & 15;
        float s = b2[o];
        #pragma unroll
        for (int ci = 0; ci < 4; ci++)
            #pragma unroll
            for (int m = 0; m < 2; m++) {
                float2 xv = ((const float2*)&S[A1_ + ci*1024 + (2*r+m)*32])[c];
                s += xv.x * w2[o*16 + ci*4 + m*2] + xv.y * w2[o*16 + ci*4 + m*2 + 1];
            }
        S[A2_ + n] = tanh_fast(s);
    }
    __syncthreads();
    // layer3: -> [16,8,8]  (1024)
    #pragma unroll
    for (int it = 0; it < 2; it++) {
        int n = tid + it * ETHREADS;
        int o = n >> 6, r = (n >> 3) & 7, c = n & 7;
        float s = b3[o];
        #pragma unroll
        for (int ci = 0; ci < 8; ci++)
            #pragma unroll
            for (int m = 0; m < 2; m++) {
                float2 xv = ((const float2*)&S[A2_ + ci*256 + (2*r+m)*16])[c];
                s += xv.x * w3[o*32 + ci*4 + m*2] + xv.y * w3[o*32 + ci*4 + m*2 + 1];
            }
        S[A3_ + n] = tanh_fast(s);
    }
    __syncthreads();
    // layer4: -> [16,4,4]  (256)
    if (tid < 256) {
        int n = tid;
        int o = n >> 4, r = (n >> 2) & 3, c = n & 3;
        float s = b4[o];
        #pragma unroll
        for (int ci = 0; ci < 16; ci++)
            #pragma unroll
            for (int m = 0; m < 2; m++) {
                float2 xv = ((const float2*)&S[A3_ + ci*64 + (2*r+m)*8])[c];
                s += xv.x * w4[o*64 + ci*4 + m*2] + xv.y * w4[o*64 + ci*4 + m*2 + 1];
            }
        S[A4_ + n] = tanh_fast(s);
    }
    __syncthreads();
    if (tid < 80) {
        int l = tid >> 3, seg = tid & 7;
        float s = 0.f;
        #pragma unroll
        for (int k = 0; k < 32; k++)
            s += S[A4_ + seg*32 + k] * lw[l*256 + seg*32 + k];
        S[RED_ + tid] = s;
    }
    __syncthreads();
    if (tid < LAT) {
        float s = lb[tid];
        #pragma unroll
        for (int k = 0; k < 8; k++) s += S[RED_ + tid*8 + k];
        S[Z_ + tid] = s;
    }
    __syncthreads();

    // ---- decoder, all T-1 time scales in one pass ----
    if (tid < 64) {
        float s = 0.f;
        #pragma unroll
        for (int l = 0; l < LAT; l++) s += S[Z_ + l] * dlw[tid*LAT + l];
        S[ZD_ + tid] = s;
    }
    __syncthreads();
    for (int n = tid; n < 640; n += ETHREADS) {
        int t = n >> 6, k = n & 63;
        S[H_ + n] = tanh_fast(0.1f * (float)(t + 1) * S[ZD_ + k]);
    }
    __syncthreads();
    for (int n0 = tid; n0 < 1280; n0 += ETHREADS) {
        int t = n0 >> 7, r = n0 & 127;
        int o = r >> 4, p = (r >> 2) & 3, q = r & 3;
        float s = 0.f;
        #pragma unroll
        for (int c = 0; c < 16; c++)
            s += S[H_ + t*64 + c*4 + (p>>1)*2 + (q>>1)]
               * dw1[c*32 + o*4 + (1-(p&1))*2 + (1-(q&1))];
        S[O1_ + n0] = tanh_fast(s);
    }
    __syncthreads();
    for (int n0 = tid; n0 < 2560; n0 += ETHREADS) {
        int t = n0 >> 8, r = n0 & 255;
        int o = r >> 6, p = (r >> 3) & 7, q = r & 7;
        float s = 0.f;
        #pragma unroll
        for (int c = 0; c < 8; c++)
            s += S[O1_ + t*128 + c*16 + (p>>1)*4 + (q>>1)]
               * dw2[c*16 + o*4 + (1-(p&1))*2 + (1-(q&1))];
        S[O2_ + n0] = tanh_fast(s);
    }
    __syncthreads();
    for (int n0 = tid; n0 < 5120; n0 += ETHREADS) {
        int t = n0 >> 9, r = n0 & 511;
        int o = r >> 8, p = (r >> 4) & 15, q = r & 15;
        float s = 0.f;
        #pragma unroll
        for (int c = 0; c < 4; c++)
            s += S[O2_ + t*256 + c*64 + (p>>1)*8 + (q>>1)]
               * dw3[c*8 + o*4 + (1-(p&1))*2 + (1-(q&1))];
        S[VF_ + n0] = s;
    }
    __syncthreads();
    float* cc = g_coef + (size_t)b * COEF_PER_BATCH;
    const float Sc = 0.3f;
    for (int n0 = tid; n0 < 2560; n0 += ETHREADS) {
        int t = n0 >> 8, cell = n0 & 255;
        int i = cell >> 4, j = cell & 15;
        int i2 = min(i + 1, 15), j2 = min(j + 1, 15);
        const float* vf = &S[VF_ + t*512];
        float v00x = vf[i*16 + j],    v00y = vf[256 + i*16 + j];
        float v10x = vf[i2*16 + j],   v10y = vf[256 + i2*16 + j];
        float v01x = vf[i*16 + j2],   v01y = vf[256 + i*16 + j2];
        float v11x = vf[i2*16 + j2],  v11y = vf[256 + i2*16 + j2];
        float c00x = Sc*v00x,                       c00y = Sc*v00y;
        float c10x = Sc*(v10x - v00x),              c10y = Sc*(v10y - v00y);
        float c01x = Sc*(v01x - v00x),              c01y = Sc*(v01y - v00y);
        float c11x = Sc*(v11x - v01x - v10x + v00x), c11y = Sc*(v11y - v01y - v10y + v00y);
        float fi = (float)i, fj = (float)j;
        // absolute form: vel(u,v) = d00 + u*d10 + v*d01 + uv*d11
        float d00x = c00x - fi*c10x - fj*c01x + fi*fj*c11x;
        float d00y = c00y - fi*c10y - fj*c01y + fi*fj*c11y;
        float d10x = c10x - fj*c11x,  d10y = c10y - fj*c11y;
        float d01x = c01x - fi*c11x,  d01y = c01y - fi*c11y;
        float4 ca = make_float4(d00x, d00y, d10x, d10y);
        float4 cb = make_float4(d01x, d01y, c11x, c11y);
        float4* d = (float4*)(cc + (t*256 + cell) * 8);
        d[0] = ca; d[1] = cb;
    }
}

// ============================================================================
// Integration over cell-sorted points, 2 points per thread for ILP.
// Absolute-coefficient step: no fu/fv computation, ~17 instr/step.
// ============================================================================
__device__ __forceinline__ void euler_step(const float* sc, int t,
                                           float& u, float& v)
{
    int ui = __float2int_rd(u);
    int vi = __float2int_rd(v);
    int idx = min(max(ui * 16 + vi, 0), 255);   // smem-bounds guard
    const float4* c = (const float4*)&sc[(t << 11) + (idx << 3)];
    float4 ca = c[0];   // d00x d00y d10x d10y
    float4 cb = c[1];   // d01x d01y d11x d11y
    float uv = u * v;
    float du = ca.x + u*ca.z + v*cb.x + uv*cb.z;
    float dv = ca.y + u*ca.w + v*cb.y + uv*cb.w;
    u += du;
    v += dv;
}

__global__ __launch_bounds__(ITHREADS, 2)
void integrate_kernel(float* __restrict__ out)
{
    extern __shared__ float sc[];     // 20480 floats: [t][cell][8]
    const int b   = blockIdx.x / BPB;
    const int blk = blockIdx.x % BPB;

    const float4* src = (const float4*)(g_coef + (size_t)b * COEF_PER_BATCH);
    float4* dst = (float4*)sc;
    #pragma unroll
    for (int i = 0; i < COEF_PER_BATCH / 4 / ITHREADS; i++)
        dst[threadIdx.x + i * ITHREADS] = src[threadIdx.x + i * ITHREADS];
    __syncthreads();

    float2* op2 = (float2*)out + (size_t)b * NPTS;
    const int pend = blk * PPB + PPB;
    for (int p0 = blk * PPB + threadIdx.x; p0 < pend; p0 += 2 * ITHREADS) {
        const int p1 = p0 + ITHREADS;
        const bool has1 = p1 < pend;
        float2 A = g_tps[p0];
        float2 Bp = has1 ? g_tps[p1] : make_float2(0.f, 0.f);
        int oa = g_order[p0];
        int ob = has1 ? g_order[p1] : 0;
        float ua = (A.x + 2.5f) * 3.0f,  va = (A.y + 2.5f) * 3.0f;
        float ub = (Bp.x + 2.5f) * 3.0f, vb = (Bp.y + 2.5f) * 3.0f;
        #pragma unroll
        for (int t = 0; t < TSTEPS; t++) {
            euler_step(sc, t, ua, va);
            euler_step(sc, t, ub, vb);
        }
        op2[oa] = make_float2(ua * (1.0f/3.0f) - 2.5f, va * (1.0f/3.0f) - 2.5f);
        if (has1)
            op2[ob] = make_float2(ub * (1.0f/3.0f) - 2.5f, vb * (1.0f/3.0f) - 2.5f);
    }
}

// ============================================================================
extern "C" void kernel_launch(void* const* d_in, const int* in_sizes, int n_in,
                              void* d_out, int out_size)
{
    const float* obs   = (const float*)d_in[0];
    const float* tpl   = (const float*)d_in[1];
    const float* ew1   = (const float*)d_in[2];
    const float* eb1   = (const float*)d_in[3];
    const float* ew2   = (const float*)d_in[4];
    const float* eb2   = (const float*)d_in[5];
    const float* ew3   = (const float*)d_in[6];
    const float* eb3   = (const float*)d_in[7];
    const float* ew4   = (const float*)d_in[8];
    const float* eb4   = (const float*)d_in[9];
    const float* elw   = (const float*)d_in[10];
    const float* elb   = (const float*)d_in[11];
    const float* dlw   = (const float*)d_in[12];
    const float* dw1   = (const float*)d_in[13];
    const float* dw2   = (const float*)d_in[14];
    const float* dw3   = (const float*)d_in[15];
    float* out = (float*)d_out;

    cudaFuncSetAttribute(integrate_kernel,
                         cudaFuncAttributeMaxDynamicSharedMemorySize,
                         COEF_PER_BATCH * 4);

    sort_count_kernel<<<NSBLK, 512>>>(tpl);
    sort_scan_kernel<<<1, 256>>>();
    sort_scatter_kernel<<<NSBLK, 512>>>(tpl);
    encdec_kernel<<<BATCH, ETHREADS>>>(obs, ew1, eb1, ew2, eb2, ew3, eb3, ew4, eb4,
                                       elw, elb, dlw, dw1, dw2, dw3);
    integrate_kernel<<<BATCH * BPB, ITHREADS, COEF_PER_BATCH * 4>>>(out);
}

// round 16
// speedup vs baseline: 1.4284x; 1.0234x over previous
#include <cuda_runtime.h>
#include <math.h>

#define BATCH   256
#define NPTS    20000
#define TSTEPS  10
#define LAT     10
#define BPB     5              // integrate blocks per batch (R11-proven)
#define PPB     (NPTS / BPB)   // 4000 points per block
#define ITHREADS 512
#define ETHREADS 512
#define COEF_PER_BATCH (TSTEPS * 256 * 8)   // 20480 floats = 80 KB
#define NSBLK   40             // sort blocks: 40*512 >= NPTS

// ---- device scratch (no allocations allowed) ----
__device__ float  g_coef[BATCH * COEF_PER_BATCH];   // [b][t][cell(16x16)][8] absolute-form
__device__ int    g_order[NPTS];
__device__ float2 g_tps[NPTS];
__device__ int    g_bhist[NSBLK][256];
__device__ int    g_bbase[NSBLK][256];

__device__ __forceinline__ float tanh_fast(float x) {
    float y;
    asm("tanh.approx.f32 %0, %1;" : "=f"(y) : "f"(x));
    return y;
}

__device__ __forceinline__ int cell_of(float2 P) {
    int ui = min(max(__float2int_rd((P.x + 2.5f) * 3.0f), 0), 15);
    int vi = min(max(__float2int_rd((P.y + 2.5f) * 3.0f), 0), 15);
    return ui * 16 + vi;
}

// ============================================================================
// Counting sort by initial grid cell — 3 kernels, NO global atomics.
// ============================================================================
__global__ void sort_count_kernel(const float* __restrict__ tpl)
{
    __shared__ int lh[256];
    const int tid = threadIdx.x;
    if (tid < 256) lh[tid] = 0;
    __syncthreads();
    int p = blockIdx.x * 512 + tid;
    if (p < NPTS) atomicAdd(&lh[cell_of(((const float2*)tpl)[p])], 1);
    __syncthreads();
    if (tid < 256) g_bhist[blockIdx.x][tid] = lh[tid];
}

__global__ void sort_scan_kernel()
{
    __shared__ int tmp[256];
    const int c = threadIdx.x;
    int total = 0;
    #pragma unroll
    for (int bk = 0; bk < NSBLK; bk++) total += g_bhist[bk][c];
    tmp[c] = total;
    __syncthreads();
    #pragma unroll
    for (int off = 1; off < 256; off <<= 1) {
        int x = (c >= off) ? tmp[c - off] : 0;
        __syncthreads();
        tmp[c] += x;
        __syncthreads();
    }
    int running = tmp[c] - total;
    #pragma unroll
    for (int bk = 0; bk < NSBLK; bk++) {
        g_bbase[bk][c] = running;
        running += g_bhist[bk][c];
    }
}

__global__ void sort_scatter_kernel(const float* __restrict__ tpl)
{
    __shared__ int lh[256];
    __shared__ int lbase[256];
    const int tid = threadIdx.x;
    if (tid < 256) {
        lh[tid] = 0;
        lbase[tid] = g_bbase[blockIdx.x][tid];
    }
    __syncthreads();
    int p = blockIdx.x * 512 + tid;
    if (p < NPTS) {
        float2 P = ((const float2*)tpl)[p];
        int c = cell_of(P);
        int idx = lbase[c] + atomicAdd(&lh[c], 1);
        g_order[idx] = p;
        g_tps[idx] = P;
    }
}

// ============================================================================
// Fused encoder + decoder + coefficient build.
// NEW: all weights prefetched to dynamic smem at block start (kills the
// 12x per-phase uniform-load L2 stalls; L1 is flushed per launch).
// Dynamic smem = weights (5632 floats) + activation union (12288) = 70 KB.
// Epilogue emits absolute-form coefficients with the identity folded in:
//   u' = d00x + u*(1+d10x) + v*d01x + uv*d11x   (ca.z holds 1+d10x)
//   v' = d00y + u*d10y + v*(1+d01y) + uv*d11y   (cb.y holds 1+d01y)
// ============================================================================
#define W1_   0
#define B1_   32
#define W2_   36
#define B2_   164
#define W3_   172
#define B3_   684
#define W4_   700
#define B4_   1724
#define LW_   1740
#define LB_   4300
#define DLW_  4310
#define DW1_  4950
#define DW2_  5462
#define DW3_  5590
#define WTOT  5632

#define OBS_  0
#define A1_   8192
#define A2_   0
#define A3_   2048
#define A4_   3072
#define RED_  11800
#define Z_    11900
#define ZD_   11910
#define H_    0
#define O1_   640
#define O2_   1920
#define VF_   4480

#define ESMEM ((WTOT + 12288) * 4)   // 71680 bytes

__global__ __launch_bounds__(ETHREADS)
void encdec_kernel(const float* __restrict__ obs,
    const float* __restrict__ w1, const float* __restrict__ b1,
    const float* __restrict__ w2, const float* __restrict__ b2,
    const float* __restrict__ w3, const float* __restrict__ b3,
    const float* __restrict__ w4, const float* __restrict__ b4,
    const float* __restrict__ lw, const float* __restrict__ lb,
    const float* __restrict__ dlw,
    const float* __restrict__ dw1, const float* __restrict__ dw2,
    const float* __restrict__ dw3)
{
    extern __shared__ float DS[];
    float* S = DS + WTOT;
    const int b = blockIdx.x;
    const int tid = threadIdx.x;

    // -- weight prefetch (batched, MLP-covered) --
    #define CPY(off, src, n) for (int i = tid; i < (n); i += ETHREADS) DS[(off)+i] = src[i];
    CPY(W1_, w1, 32)   CPY(B1_, b1, 4)    CPY(W2_, w2, 128)  CPY(B2_, b2, 8)
    CPY(W3_, w3, 512)  CPY(B3_, b3, 16)   CPY(W4_, w4, 1024) CPY(B4_, b4, 16)
    CPY(LW_, lw, 2560) CPY(LB_, lb, 10)   CPY(DLW_, dlw, 640)
    CPY(DW1_, dw1, 512) CPY(DW2_, dw2, 128) CPY(DW3_, dw3, 32)
    #undef CPY

    // -- obs staging (coalesced float4) --
    {
        const float4* src = (const float4*)(obs + (size_t)b * 8192);
        float4* dst = (float4*)&S[OBS_];
        #pragma unroll
        for (int i = 0; i < 4; i++) dst[tid + i * ETHREADS] = src[tid + i * ETHREADS];
    }
    __syncthreads();

    // layer1: [2,64,64] -> [4,32,32]  (4096 outputs)
    #pragma unroll
    for (int it = 0; it < 8; it++) {
        int n = tid + it * ETHREADS;
        int o = n >> 10, r = (n >> 5) & 31, c = n & 31;
        float s = DS[B1_ + o];
        #pragma unroll
        for (int ci = 0; ci < 2; ci++)
            #pragma unroll
            for (int m = 0; m < 2; m++) {
                float2 xv = ((const float2*)&S[OBS_ + ci*4096 + (2*r+m)*64])[c];
                s += xv.x * DS[W1_ + o*8 + ci*4 + m*2] + xv.y * DS[W1_ + o*8 + ci*4 + m*2 + 1];
            }
        S[A1_ + n] = tanh_fast(s);
    }
    __syncthreads();
    // layer2: -> [8,16,16]  (2048)
    #pragma unroll
    for (int it = 0; it < 4; it++) {
        int n = tid + it * ETHREADS;
        int o = n >> 8, r = (n >> 4) & 15, c = n & 15;
        float s = DS[B2_ + o];
        #pragma unroll
        for (int ci = 0; ci < 4; ci++)
            #pragma unroll
            for (int m = 0; m < 2; m++) {
                float2 xv = ((const float2*)&S[A1_ + ci*1024 + (2*r+m)*32])[c];
                s += xv.x * DS[W2_ + o*16 + ci*4 + m*2] + xv.y * DS[W2_ + o*16 + ci*4 + m*2 + 1];
            }
        S[A2_ + n] = tanh_fast(s);
    }
    __syncthreads();
    // layer3: -> [16,8,8]  (1024)
    #pragma unroll
    for (int it = 0; it < 2; it++) {
        int n = tid + it * ETHREADS;
        int o = n >> 6, r = (n >> 3) & 7, c = n & 7;
        float s = DS[B3_ + o];
        #pragma unroll
        for (int ci = 0; ci < 8; ci++)
            #pragma unroll
            for (int m = 0; m < 2; m++) {
                float2 xv = ((const float2*)&S[A2_ + ci*256 + (2*r+m)*16])[c];
                s += xv.x * DS[W3_ + o*32 + ci*4 + m*2] + xv.y * DS[W3_ + o*32 + ci*4 + m*2 + 1];
            }
        S[A3_ + n] = tanh_fast(s);
    }
    __syncthreads();
    // layer4: -> [16,4,4]  (256)
    if (tid < 256) {
        int n = tid;
        int o = n >> 4, r = (n >> 2) & 3, c = n & 3;
        float s = DS[B4_ + o];
        #pragma unroll
        for (int ci = 0; ci < 16; ci++)
            #pragma unroll
            for (int m = 0; m < 2; m++) {
                float2 xv = ((const float2*)&S[A3_ + ci*64 + (2*r+m)*8])[c];
                s += xv.x * DS[W4_ + o*64 + ci*4 + m*2] + xv.y * DS[W4_ + o*64 + ci*4 + m*2 + 1];
            }
        S[A4_ + n] = tanh_fast(s);
    }
    __syncthreads();
    if (tid < 80) {
        int l = tid >> 3, seg = tid & 7;
        float s = 0.f;
        #pragma unroll
        for (int k = 0; k < 32; k++)
            s += S[A4_ + seg*32 + k] * DS[LW_ + l*256 + seg*32 + k];
        S[RED_ + tid] = s;
    }
    __syncthreads();
    if (tid < LAT) {
        float s = DS[LB_ + tid];
        #pragma unroll
        for (int k = 0; k < 8; k++) s += S[RED_ + tid*8 + k];
        S[Z_ + tid] = s;
    }
    __syncthreads();

    // ---- decoder, all T-1 time scales in one pass ----
    if (tid < 64) {
        float s = 0.f;
        #pragma unroll
        for (int l = 0; l < LAT; l++) s += S[Z_ + l] * DS[DLW_ + tid*LAT + l];
        S[ZD_ + tid] = s;
    }
    __syncthreads();
    for (int n = tid; n < 640; n += ETHREADS) {
        int t = n >> 6, k = n & 63;
        S[H_ + n] = tanh_fast(0.1f * (float)(t + 1) * S[ZD_ + k]);
    }
    __syncthreads();
    for (int n0 = tid; n0 < 1280; n0 += ETHREADS) {
        int t = n0 >> 7, r = n0 & 127;
        int o = r >> 4, p = (r >> 2) & 3, q = r & 3;
        float s = 0.f;
        #pragma unroll
        for (int c = 0; c < 16; c++)
            s += S[H_ + t*64 + c*4 + (p>>1)*2 + (q>>1)]
               * DS[DW1_ + c*32 + o*4 + (1-(p&1))*2 + (1-(q&1))];
        S[O1_ + n0] = tanh_fast(s);
    }
    __syncthreads();
    for (int n0 = tid; n0 < 2560; n0 += ETHREADS) {
        int t = n0 >> 8, r = n0 & 255;
        int o = r >> 6, p = (r >> 3) & 7, q = r & 7;
        float s = 0.f;
        #pragma unroll
        for (int c = 0; c < 8; c++)
            s += S[O1_ + t*128 + c*16 + (p>>1)*4 + (q>>1)]
               * DS[DW2_ + c*16 + o*4 + (1-(p&1))*2 + (1-(q&1))];
        S[O2_ + n0] = tanh_fast(s);
    }
    __syncthreads();
    for (int n0 = tid; n0 < 5120; n0 += ETHREADS) {
        int t = n0 >> 9, r = n0 & 511;
        int o = r >> 8, p = (r >> 4) & 15, q = r & 15;
        float s = 0.f;
        #pragma unroll
        for (int c = 0; c < 4; c++)
            s += S[O2_ + t*256 + c*64 + (p>>1)*8 + (q>>1)]
               * DS[DW3_ + c*8 + o*4 + (1-(p&1))*2 + (1-(q&1))];
        S[VF_ + n0] = s;
    }
    __syncthreads();
    float* cc = g_coef + (size_t)b * COEF_PER_BATCH;
    const float Sc = 0.3f;
    for (int n0 = tid; n0 < 2560; n0 += ETHREADS) {
        int t = n0 >> 8, cell = n0 & 255;
        int i = cell >> 4, j = cell & 15;
        int i2 = min(i + 1, 15), j2 = min(j + 1, 15);
        const float* vf = &S[VF_ + t*512];
        float v00x = vf[i*16 + j],    v00y = vf[256 + i*16 + j];
        float v10x = vf[i2*16 + j],   v10y = vf[256 + i2*16 + j];
        float v01x = vf[i*16 + j2],   v01y = vf[256 + i*16 + j2];
        float v11x = vf[i2*16 + j2],  v11y = vf[256 + i2*16 + j2];
        float c00x = Sc*v00x,                       c00y = Sc*v00y;
        float c10x = Sc*(v10x - v00x),              c10y = Sc*(v10y - v00y);
        float c01x = Sc*(v01x - v00x),              c01y = Sc*(v01y - v00y);
        float c11x = Sc*(v11x - v01x - v10x + v00x), c11y = Sc*(v11y - v01y - v10y + v00y);
        float fi = (float)i, fj = (float)j;
        float d00x = c00x - fi*c10x - fj*c01x + fi*fj*c11x;
        float d00y = c00y - fi*c10y - fj*c01y + fi*fj*c11y;
        float d10x = c10x - fj*c11x,  d10y = c10y - fj*c11y;
        float d01x = c01x - fi*c11x,  d01y = c01y - fi*c11y;
        // identity folded: ca.z = 1+d10x (u's u-coef), cb.y = 1+d01y (v's v-coef)
        float4 ca = make_float4(d00x, d00y, d10x + 1.0f, d10y);
        float4 cb = make_float4(d01x, d01y + 1.0f, c11x, c11y);
        float4* d = (float4*)(cc + (t*256 + cell) * 8);
        d[0] = ca; d[1] = cb;
    }
}

// ============================================================================
// Integration over cell-sorted points, 2 points per thread for ILP.
// Absolute-coefficient step with identity folded: pure FFMA map, ~15 instr.
// ============================================================================
__device__ __forceinline__ void euler_step(const float* sc, int t,
                                           float& u, float& v)
{
    int ui = __float2int_rd(u);
    int vi = __float2int_rd(v);
    int idx = min(max(ui * 16 + vi, 0), 255);   // smem-bounds guard
    const float4* c = (const float4*)&sc[(t << 11) + (idx << 3)];
    float4 ca = c[0];   // d00x d00y (1+d10x) d10y
    float4 cb = c[1];   // d01x (1+d01y) d11x d11y
    float uv = u * v;
    float un = ca.x + u*ca.z + v*cb.x + uv*cb.z;
    float vn = ca.y + u*ca.w + v*cb.y + uv*cb.w;
    u = un;
    v = vn;
}

__global__ __launch_bounds__(ITHREADS, 2)
void integrate_kernel(float* __restrict__ out)
{
    extern __shared__ float sc[];     // 20480 floats: [t][cell][8]
    const int b   = blockIdx.x / BPB;
    const int blk = blockIdx.x % BPB;

    const float4* src = (const float4*)(g_coef + (size_t)b * COEF_PER_BATCH);
    float4* dst = (float4*)sc;
    #pragma unroll
    for (int i = 0; i < COEF_PER_BATCH / 4 / ITHREADS; i++)
        dst[threadIdx.x + i * ITHREADS] = src[threadIdx.x + i * ITHREADS];
    __syncthreads();

    float2* op2 = (float2*)out + (size_t)b * NPTS;
    const int pend = blk * PPB + PPB;
    for (int p0 = blk * PPB + threadIdx.x; p0 < pend; p0 += 2 * ITHREADS) {
        const int p1 = p0 + ITHREADS;
        const bool has1 = p1 < pend;
        float2 A = g_tps[p0];
        float2 Bp = has1 ? g_tps[p1] : make_float2(0.f, 0.f);
        int oa = g_order[p0];
        int ob = has1 ? g_order[p1] : 0;
        float ua = (A.x + 2.5f) * 3.0f,  va = (A.y + 2.5f) * 3.0f;
        float ub = (Bp.x + 2.5f) * 3.0f, vb = (Bp.y + 2.5f) * 3.0f;
        #pragma unroll
        for (int t = 0; t < TSTEPS; t++) {
            euler_step(sc, t, ua, va);
            euler_step(sc, t, ub, vb);
        }
        op2[oa] = make_float2(ua * (1.0f/3.0f) - 2.5f, va * (1.0f/3.0f) - 2.5f);
        if (has1)
            op2[ob] = make_float2(ub * (1.0f/3.0f) - 2.5f, vb * (1.0f/3.0f) - 2.5f);
    }
}

// ============================================================================
extern "C" void kernel_launch(void* const* d_in, const int* in_sizes, int n_in,
                              void* d_out, int out_size)
{
    const float* obs   = (const float*)d_in[0];
    const float* tpl   = (const float*)d_in[1];
    const float* ew1   = (const float*)d_in[2];
    const float* eb1   = (const float*)d_in[3];
    const float* ew2   = (const float*)d_in[4];
    const float* eb2   = (const float*)d_in[5];
    const float* ew3   = (const float*)d_in[6];
    const float* eb3   = (const float*)d_in[7];
    const float* ew4   = (const float*)d_in[8];
    const float* eb4   = (const float*)d_in[9];
    const float* elw   = (const float*)d_in[10];
    const float* elb   = (const float*)d_in[11];
    const float* dlw   = (const float*)d_in[12];
    const float* dw1   = (const float*)d_in[13];
    const float* dw2   = (const float*)d_in[14];
    const float* dw3   = (const float*)d_in[15];
    float* out = (float*)d_out;

    cudaFuncSetAttribute(integrate_kernel,
                         cudaFuncAttributeMaxDynamicSharedMemorySize,
                         COEF_PER_BATCH * 4);
    cudaFuncSetAttribute(encdec_kernel,
                         cudaFuncAttributeMaxDynamicSharedMemorySize,
                         ESMEM);

    sort_count_kernel<<<NSBLK, 512>>>(tpl);
    sort_scan_kernel<<<1, 256>>>();
    sort_scatter_kernel<<<NSBLK, 512>>>(tpl);
    encdec_kernel<<<BATCH, ETHREADS, ESMEM>>>(obs, ew1, eb1, ew2, eb2, ew3, eb3,
                                              ew4, eb4, elw, elb, dlw, dw1, dw2, dw3);
    integrate_kernel<<<BATCH * BPB, ITHREADS, COEF_PER_BATCH * 4>>>(out);
}